// round 10
// baseline (speedup 1.0000x reference)
#include <cuda_runtime.h>
#include <cstdint>

// Fixed shapes: preds/targets [32, 2048, 512] f32, lengths [32] i32.
#define BB 32
#define TT 2048
#define DD 512
#define CHUNK 32         // rows per block (contiguous); 64 chunks per b
#define NCH 64           // chunks per b; grid = 64 x 32
#define SROWS 4          // rows per pipeline stage
#define STAGES 4         // ring depth
#define PRE 3            // stages in flight
#define STAGE_F4 1024    // 4 rows x 2 tensors x 128 float4 = 16KB
#define ROW_BYTES 2048

// Scratch (device globals; every slot rewritten each launch; counters wrap
// back to 0 -> graph-replay-safe, no init kernel).
__device__ float    g_S[BB * NCH * DD];   // per-(b,chunk,d) diff-sum partials, 4 MiB
__device__ float    g_wordP[BB * NCH];    // per-block word-loss partials
__device__ float    g_sentB[BB];          // per-b sentence term
__device__ unsigned g_ctrB[BB];           // per-b arrival counters (wrap at NCH-1)
__device__ unsigned g_ctr;                // global arrival counter (wrap at BB-1)

__device__ __forceinline__ float sl1(float d) {
    float ad = fabsf(d);
    return ad < 1.0f ? 0.5f * d * d : ad - 0.5f;
}

__device__ __forceinline__ unsigned smem_u32(const void* p) {
    return (unsigned)__cvta_generic_to_shared(p);
}

#define MBAR_INIT(a, c) \
    asm volatile("mbarrier.init.shared.b64 [%0], %1;" :: "r"(a), "r"(c) : "memory")
#define MBAR_EXPECT(a, bytes) \
    asm volatile("mbarrier.arrive.expect_tx.shared.b64 _, [%0], %1;" :: "r"(a), "r"(bytes) : "memory")
#define BULK_G2S(dst, src, n, mb) \
    asm volatile("cp.async.bulk.shared::cluster.global.mbarrier::complete_tx::bytes [%0], [%1], %2, [%3];" \
                 :: "r"(dst), "l"(src), "r"(n), "r"(mb) : "memory")
#define MBAR_WAIT(mb, ph) do {                                              \
    unsigned _done = 0;                                                     \
    while (!_done) {                                                        \
        asm volatile("{\n\t.reg .pred p;\n\t"                               \
                     "mbarrier.try_wait.parity.shared::cta.b64 p, [%1], %2;\n\t" \
                     "selp.b32 %0, 1, 0, p;\n\t}"                           \
                     : "=r"(_done) : "r"(mb), "r"(ph) : "memory");          \
    }                                                                       \
} while (0)

// grid = (NCH, BB), block = 256. Streaming via cp.async.bulk (TMA path):
// 16KB stages (4 rows x {preds,targs}) land in smem, mbarrier-completed.
__global__ __launch_bounds__(256)
void k_fused(const float* __restrict__ preds,
             const float* __restrict__ targs,
             const int* __restrict__ lens,
             float* __restrict__ out) {
    extern __shared__ float4 dynbuf[];    // STAGES * 16KB
    __shared__ uint64_t mbar[STAGES];
    __shared__ float4 sh4[128];
    __shared__ float  sw[256];
    __shared__ bool   is_last_b, is_last_g;

    const int b   = blockIdx.y;
    const int c   = blockIdx.x;
    const int tid = threadIdx.x;
    const int sub = tid >> 7;             // 0/1
    const int lane = tid & 127;
    const int dg   = lane << 2;

    const int len  = lens[b];
    const int t0   = c * CHUNK;
    const int rows = max(0, min(t0 + CHUNK, len) - t0);
    const int NS   = (rows + SROWS - 1) >> 2;   // stages (<= 8)

    float4 sd = make_float4(0.f, 0.f, 0.f, 0.f);
    float  w  = 0.f;

    if (NS > 0) {
        if (tid == 0) {
            #pragma unroll
            for (int s = 0; s < STAGES; s++) MBAR_INIT(smem_u32(&mbar[s]), 1);
        }
        __syncthreads();

        const char* psrc = (const char*)(preds + ((size_t)b * TT + t0) * DD);
        const char* qsrc = (const char*)(targs + ((size_t)b * TT + t0) * DD);

        // issue stage k into slot k&3
        auto issue = [&](int k) {
            const int rs = min(SROWS, rows - (k << 2));
            const unsigned bytes = (unsigned)(rs * ROW_BYTES);
            const int slot = k & (STAGES - 1);
            const unsigned mb = smem_u32(&mbar[slot]);
            MBAR_EXPECT(mb, 2u * bytes);
            const unsigned d0 = smem_u32(&dynbuf[slot * STAGE_F4]);
            BULK_G2S(d0,                     psrc + (size_t)(k << 2) * ROW_BYTES, bytes, mb);
            BULK_G2S(d0 + SROWS * ROW_BYTES, qsrc + (size_t)(k << 2) * ROW_BYTES, bytes, mb);
        };

        if (tid == 0) {
            #pragma unroll
            for (int k = 0; k < PRE; k++) if (k < NS) issue(k);
        }

        for (int k = 0; k < NS; k++) {
            const int slot = k & (STAGES - 1);
            MBAR_WAIT(smem_u32(&mbar[slot]), (k >> 2) & 1);
            const int rs = min(SROWS, rows - (k << 2));
            const float4* sp = &dynbuf[slot * STAGE_F4];
            const float4* sq = sp + SROWS * 128;
            for (int lr = sub; lr < rs; lr += 2) {
                const float4 pv = sp[lr * 128 + lane];
                const float4 tv = sq[lr * 128 + lane];
                float dx = pv.x - tv.x, dy = pv.y - tv.y;
                float dz = pv.z - tv.z, dw = pv.w - tv.w;
                sd.x += dx; sd.y += dy; sd.z += dz; sd.w += dw;
                w += sl1(dx) + sl1(dy) + sl1(dz) + sl1(dw);
            }
            __syncthreads();              // all consumed; slot (k+PRE)&3 is free
            if (tid == 0 && k + PRE < NS) issue(k + PRE);
        }
    }

    // Combine sub0+sub1 diff-sums; one slot per (b,chunk).
    if (sub == 1) sh4[lane] = sd;
    sw[tid] = w;
    __syncthreads();
    if (sub == 0) {
        const float4 o = sh4[lane];
        sd.x += o.x; sd.y += o.y; sd.z += o.z; sd.w += o.w;
        *reinterpret_cast<float4*>(g_S + ((size_t)(b * NCH + c)) * DD + dg) = sd;
    }

    // Block-reduce the word partial.
    #pragma unroll
    for (int s = 128; s > 0; s >>= 1) {
        if (tid < s) sw[tid] += sw[tid + s];
        __syncthreads();
    }
    if (tid == 0) {
        g_wordP[b * NCH + c] = sw[0];
        __threadfence();
        unsigned prev = atomicInc(&g_ctrB[b], NCH - 1u);   // wraps -> replay-safe
        is_last_b = (prev == NCH - 1u);
    }
    __syncthreads();
    if (!is_last_b) return;

    // ---- Phase 2 (last chunk of this b): fold NCH slots, L2-hot ----
    __threadfence();

    float4 s4 = make_float4(0.f, 0.f, 0.f, 0.f);
    const float* Sb = g_S + (size_t)b * NCH * DD;
    #pragma unroll
    for (int j = sub * (NCH / 2); j < (sub + 1) * (NCH / 2); j++) {
        const float4 v = *reinterpret_cast<const float4*>(Sb + (size_t)j * DD + dg);
        s4.x += v.x; s4.y += v.y; s4.z += v.z; s4.w += v.w;
    }
    __syncthreads();
    if (sub == 1) sh4[lane] = s4;
    __syncthreads();
    float wsent = 0.f;
    if (sub == 0) {
        const float4 o = sh4[lane];
        s4.x += o.x; s4.y += o.y; s4.z += o.z; s4.w += o.w;
        const float invlen = 1.0f / (float)len;
        wsent = sl1(s4.x * invlen) + sl1(s4.y * invlen)
              + sl1(s4.z * invlen) + sl1(s4.w * invlen);
    }
    sw[tid] = wsent;
    __syncthreads();
    #pragma unroll
    for (int s = 128; s > 0; s >>= 1) {
        if (tid < s) sw[tid] += sw[tid + s];
        __syncthreads();
    }
    if (tid == 0) {
        g_sentB[b] = sw[0] * (1.0f / (float)DD);
        __threadfence();
        unsigned prev = atomicInc(&g_ctr, BB - 1u);
        is_last_g = (prev == BB - 1u);
    }
    __syncthreads();
    if (!is_last_g) return;

    // ---- Phase 3 (single final block): scalar combine, L2-hot ----
    __threadfence();

    float wsum = 0.f;
    #pragma unroll
    for (int i = tid; i < BB * NCH; i += 256) wsum += g_wordP[i];
    float ssum = 0.f;
    int   lsum = 0;
    if (tid < BB) { ssum = g_sentB[tid]; lsum = lens[tid]; }

    __shared__ float swd[256];
    __shared__ float ssn[256];
    __shared__ int   sln[256];
    swd[tid] = wsum; ssn[tid] = ssum; sln[tid] = lsum;
    __syncthreads();
    #pragma unroll
    for (int s = 128; s > 0; s >>= 1) {
        if (tid < s) {
            swd[tid] += swd[tid + s];
            ssn[tid] += ssn[tid + s];
            sln[tid] += sln[tid + s];
        }
        __syncthreads();
    }
    if (tid == 0) {
        const float n_valid = (float)sln[0] * (float)DD;   // <= 2^25, exact
        out[0] = swd[0] / n_valid + ssn[0] * (1.0f / (float)BB);
    }
}

extern "C" void kernel_launch(void* const* d_in, const int* in_sizes, int n_in,
                              void* d_out, int out_size) {
    const float* preds = (const float*)d_in[0];
    const float* targs = (const float*)d_in[1];
    const int*   lens  = (const int*)d_in[2];
    float* out = (float*)d_out;

    const int smem = STAGES * STAGE_F4 * sizeof(float4);   // 64 KB dynamic
    cudaFuncSetAttribute(k_fused, cudaFuncAttributeMaxDynamicSharedMemorySize, smem);
    k_fused<<<dim3(NCH, BB), 256, smem>>>(preds, targs, lens, out);
}

// round 13
// speedup vs baseline: 1.1476x; 1.1476x over previous
#include <cuda_runtime.h>

// Fixed shapes: preds/targets [32, 2048, 512] f32, lengths [32] i32.
#define BB 32
#define TT 2048
#define DD 512
#define TILES 64   // blocks (t-tiles) per batch row, strided t assignment

// Scratch (device globals; every slot rewritten each launch; counters wrap
// back to 0 -> graph-replay-safe, no init kernel).
__device__ float    g_S[BB * TILES * DD];   // per-(b,tile,d) diff-sum partials, 4 MiB
__device__ float    g_wordP[BB * TILES];    // per-block word-loss partials (2048)
__device__ float    g_sentB[BB];            // per-b sentence term
__device__ unsigned g_ctrB[BB];             // per-b arrival counters (wrap at TILES-1)
__device__ unsigned g_ctr;                  // global arrival counter (wrap at BB-1)

__device__ __forceinline__ float sl1(float d) {
    float ad = fabsf(d);
    return ad < 1.0f ? 0.5f * d * d : ad - 0.5f;
}

// One fused kernel. grid = (TILES, BB), block = 256 (2 t-rows x 128 float4 lanes).
// Streaming loads use LDG.E.CV (cache-volatile): no L2 allocation for
// read-once data -- the documented path for the B300 chip-level load cap.
__global__ __launch_bounds__(256)
void k_fused(const float* __restrict__ preds,
             const float* __restrict__ targs,
             const int* __restrict__ lens,
             float* __restrict__ out) {
    const int b    = blockIdx.y;
    const int tile = blockIdx.x;
    const int tid  = threadIdx.x;
    const int sub  = tid >> 7;            // 0/1: which row of the pair
    const int lane = tid & 127;
    const int dg   = lane << 2;           // float4 column group (covers D=512)

    const int len = lens[b];

    // ---- Phase 1: stream valid rows once (HBM-bound), .cv loads ----
    float4 sd0 = make_float4(0.f, 0.f, 0.f, 0.f);
    float4 sd1 = make_float4(0.f, 0.f, 0.f, 0.f);
    float  w0 = 0.f, w1 = 0.f;

    const float* pbase = preds + (size_t)b * TT * DD + dg;
    const float* qbase = targs + (size_t)b * TT * DD + dg;
    const int step = 2 * TILES;           // 128 rows between this thread's rows

    int t = tile + sub * TILES;
    // paired main loop: 4 independent LDG.128.CV per iteration
    for (; t + step < len; t += 2 * step) {
        const size_t o0 = (size_t)t * DD;
        const size_t o1 = (size_t)(t + step) * DD;
        const float4 p0 = __ldcv(reinterpret_cast<const float4*>(pbase + o0));
        const float4 q0 = __ldcv(reinterpret_cast<const float4*>(qbase + o0));
        const float4 p1 = __ldcv(reinterpret_cast<const float4*>(pbase + o1));
        const float4 q1 = __ldcv(reinterpret_cast<const float4*>(qbase + o1));

        float ax = p0.x - q0.x, ay = p0.y - q0.y, az = p0.z - q0.z, aw = p0.w - q0.w;
        sd0.x += ax; sd0.y += ay; sd0.z += az; sd0.w += aw;
        w0 += sl1(ax) + sl1(ay) + sl1(az) + sl1(aw);

        float bx = p1.x - q1.x, by = p1.y - q1.y, bz = p1.z - q1.z, bw = p1.w - q1.w;
        sd1.x += bx; sd1.y += by; sd1.z += bz; sd1.w += bw;
        w1 += sl1(bx) + sl1(by) + sl1(bz) + sl1(bw);
    }
    if (t < len) {                        // at most one leftover row
        const size_t o0 = (size_t)t * DD;
        const float4 p0 = __ldcv(reinterpret_cast<const float4*>(pbase + o0));
        const float4 q0 = __ldcv(reinterpret_cast<const float4*>(qbase + o0));
        float ax = p0.x - q0.x, ay = p0.y - q0.y, az = p0.z - q0.z, aw = p0.w - q0.w;
        sd0.x += ax; sd0.y += ay; sd0.z += az; sd0.w += aw;
        w0 += sl1(ax) + sl1(ay) + sl1(az) + sl1(aw);
    }
    float4 sd = make_float4(sd0.x + sd1.x, sd0.y + sd1.y,
                            sd0.z + sd1.z, sd0.w + sd1.w);
    float w = w0 + w1;

    // Combine sub0+sub1 diff-sums via shared; one slot per (b,tile).
    __shared__ float4 sh4[128];
    __shared__ float  sw[256];
    __shared__ bool   is_last_b, is_last_g;
    if (sub == 1) sh4[lane] = sd;
    sw[tid] = w;
    __syncthreads();
    if (sub == 0) {
        const float4 o = sh4[lane];
        sd.x += o.x; sd.y += o.y; sd.z += o.z; sd.w += o.w;
        __stcs(reinterpret_cast<float4*>(g_S + ((size_t)(b * TILES + tile)) * DD + dg), sd);
    }

    // Block-reduce the word partial.
    #pragma unroll
    for (int s = 128; s > 0; s >>= 1) {
        if (tid < s) sw[tid] += sw[tid + s];
        __syncthreads();
    }
    if (tid == 0) {
        g_wordP[b * TILES + tile] = sw[0];
        __threadfence();
        // wraps to 0 after TILES arrivals -> self-resetting across replays
        unsigned prev = atomicInc(&g_ctrB[b], TILES - 1u);
        is_last_b = (prev == TILES - 1u);
    }
    __syncthreads();
    if (!is_last_b) return;

    // ---- Phase 2 (last block of this b): fold 64 partial slots, L2-hot ----
    __threadfence();  // acquire: see all 64 blocks' g_S writes for this b

    float4 s4 = make_float4(0.f, 0.f, 0.f, 0.f);
    const float* Sb = g_S + (size_t)b * TILES * DD;
    #pragma unroll
    for (int j = sub * (TILES / 2); j < (sub + 1) * (TILES / 2); j++) {
        const float4 v = *reinterpret_cast<const float4*>(Sb + (size_t)j * DD + dg);
        s4.x += v.x; s4.y += v.y; s4.z += v.z; s4.w += v.w;
    }
    __syncthreads();   // sh4 reuse
    if (sub == 1) sh4[lane] = s4;
    __syncthreads();
    float wsent = 0.f;
    if (sub == 0) {
        const float4 o = sh4[lane];
        s4.x += o.x; s4.y += o.y; s4.z += o.z; s4.w += o.w;
        const float invlen = 1.0f / (float)len;
        wsent = sl1(s4.x * invlen) + sl1(s4.y * invlen)
              + sl1(s4.z * invlen) + sl1(s4.w * invlen);
    }
    sw[tid] = wsent;
    __syncthreads();
    #pragma unroll
    for (int s = 128; s > 0; s >>= 1) {
        if (tid < s) sw[tid] += sw[tid + s];
        __syncthreads();
    }
    if (tid == 0) {
        g_sentB[b] = sw[0] * (1.0f / (float)DD);
        __threadfence();
        unsigned prev = atomicInc(&g_ctr, BB - 1u);
        is_last_g = (prev == BB - 1u);
    }
    __syncthreads();
    if (!is_last_g) return;

    // ---- Phase 3 (single final block): scalar combine, L2-hot ----
    __threadfence();

    float wsum = 0.f;
    #pragma unroll
    for (int i = tid; i < BB * TILES; i += 256) wsum += g_wordP[i];
    float ssum = 0.f;
    int   lsum = 0;
    if (tid < BB) { ssum = g_sentB[tid]; lsum = lens[tid]; }

    __shared__ float swd[256];
    __shared__ float ssn[256];
    __shared__ int   sln[256];
    swd[tid] = wsum; ssn[tid] = ssum; sln[tid] = lsum;
    __syncthreads();
    #pragma unroll
    for (int s = 128; s > 0; s >>= 1) {
        if (tid < s) {
            swd[tid] += swd[tid + s];
            ssn[tid] += ssn[tid + s];
            sln[tid] += sln[tid + s];
        }
        __syncthreads();
    }
    if (tid == 0) {
        const float n_valid = (float)sln[0] * (float)DD;  // <= 2^25, exact
        out[0] = swd[0] / n_valid + ssn[0] * (1.0f / (float)BB);
    }
}

extern "C" void kernel_launch(void* const* d_in, const int* in_sizes, int n_in,
                              void* d_out, int out_size) {
    const float* preds = (const float*)d_in[0];
    const float* targs = (const float*)d_in[1];
    const int*   lens  = (const int*)d_in[2];
    float* out = (float*)d_out;

    k_fused<<<dim3(TILES, BB), 256>>>(preds, targs, lens, out);
}

// round 15
// speedup vs baseline: 1.3129x; 1.1440x over previous
#include <cuda_runtime.h>

// Fixed shapes: preds/targets [32, 2048, 512] f32, lengths [32] i32.
#define BB 32
#define TT 2048
#define DD 512
#define TILES 64   // blocks (t-tiles) per batch row, strided t assignment
#define PFD 256    // prefetch distance in rows (one tid0 iteration ahead)

// Scratch (device globals; every slot rewritten each launch; counters wrap
// back to 0 -> graph-replay-safe, no init kernel).
__device__ float    g_S[BB * TILES * DD];   // per-(b,tile,d) diff-sum partials, 4 MiB
__device__ float    g_wordP[BB * TILES];    // per-block word-loss partials (2048)
__device__ float    g_sentB[BB];            // per-b sentence term
__device__ unsigned g_ctrB[BB];             // per-b arrival counters (wrap at TILES-1)
__device__ unsigned g_ctr;                  // global arrival counter (wrap at BB-1)

__device__ __forceinline__ float sl1(float d) {
    float ad = fabsf(d);
    return ad < 1.0f ? 0.5f * d * d : ad - 0.5f;
}

// Fire-and-forget bulk L2 prefetch (no completion tracking).
__device__ __forceinline__ void pf_l2(const void* p, unsigned bytes) {
    asm volatile("cp.async.bulk.prefetch.L2.global [%0], %1;"
                 :: "l"(p), "r"(bytes) : "memory");
}

// One fused kernel. grid = (TILES, BB), block = 256 (2 t-rows x 128 float4 lanes).
// DRAM fill is driven by bulk L2 prefetches (untracked); demand loads are
// evict-first and hit L2.
__global__ __launch_bounds__(256)
void k_fused(const float* __restrict__ preds,
             const float* __restrict__ targs,
             const int* __restrict__ lens,
             float* __restrict__ out) {
    const int b    = blockIdx.y;
    const int tile = blockIdx.x;
    const int tid  = threadIdx.x;
    const int sub  = tid >> 7;            // 0/1: which row of the pair
    const int lane = tid & 127;
    const int dg   = lane << 2;           // float4 column group (covers D=512)

    const int len = lens[b];

    // ---- Phase 1: stream valid rows once ----
    float4 sd0 = make_float4(0.f, 0.f, 0.f, 0.f);
    float4 sd1 = make_float4(0.f, 0.f, 0.f, 0.f);
    float  w0 = 0.f, w1 = 0.f;

    const float* pbase = preds + (size_t)b * TT * DD + dg;   // tid0: dg=0 -> row base
    const float* qbase = targs + (size_t)b * TT * DD + dg;
    const int step = 2 * TILES;           // 128 rows between this thread's rows

    int t = tile + sub * TILES;

    // Prologue prefetch: the first iteration's rows (tid 0 only; dg==0 there).
    if (tid == 0) {
        #pragma unroll
        for (int j = 0; j < 4; j++) {
            const int r = tile + j * TILES;          // rows this block touches first
            if (r < len) {
                pf_l2(pbase + (size_t)r * DD, 2048u);
                pf_l2(qbase + (size_t)r * DD, 2048u);
            }
        }
    }

    // paired main loop: 4 independent LDG.128 per iteration + lookahead prefetch
    for (; t + step < len; t += 2 * step) {
        if (tid == 0) {
            const int pf = t + PFD;
            #pragma unroll
            for (int j = 0; j < 4; j++) {
                const int r = pf + j * TILES;        // next span's 4 block-rows
                if (r < len) {
                    pf_l2(pbase + (size_t)r * DD, 2048u);
                    pf_l2(qbase + (size_t)r * DD, 2048u);
                }
            }
        }
        const size_t o0 = (size_t)t * DD;
        const size_t o1 = (size_t)(t + step) * DD;
        const float4 p0 = __ldcs(reinterpret_cast<const float4*>(pbase + o0));
        const float4 q0 = __ldcs(reinterpret_cast<const float4*>(qbase + o0));
        const float4 p1 = __ldcs(reinterpret_cast<const float4*>(pbase + o1));
        const float4 q1 = __ldcs(reinterpret_cast<const float4*>(qbase + o1));

        float ax = p0.x - q0.x, ay = p0.y - q0.y, az = p0.z - q0.z, aw = p0.w - q0.w;
        sd0.x += ax; sd0.y += ay; sd0.z += az; sd0.w += aw;
        w0 += sl1(ax) + sl1(ay) + sl1(az) + sl1(aw);

        float bx = p1.x - q1.x, by = p1.y - q1.y, bz = p1.z - q1.z, bw = p1.w - q1.w;
        sd1.x += bx; sd1.y += by; sd1.z += bz; sd1.w += bw;
        w1 += sl1(bx) + sl1(by) + sl1(bz) + sl1(bw);
    }
    if (t < len) {                        // at most one leftover row
        const size_t o0 = (size_t)t * DD;
        const float4 p0 = __ldcs(reinterpret_cast<const float4*>(pbase + o0));
        const float4 q0 = __ldcs(reinterpret_cast<const float4*>(qbase + o0));
        float ax = p0.x - q0.x, ay = p0.y - q0.y, az = p0.z - q0.z, aw = p0.w - q0.w;
        sd0.x += ax; sd0.y += ay; sd0.z += az; sd0.w += aw;
        w0 += sl1(ax) + sl1(ay) + sl1(az) + sl1(aw);
    }
    float4 sd = make_float4(sd0.x + sd1.x, sd0.y + sd1.y,
                            sd0.z + sd1.z, sd0.w + sd1.w);
    float w = w0 + w1;

    // Combine sub0+sub1 diff-sums via shared; one slot per (b,tile).
    __shared__ float4 sh4[128];
    __shared__ float  sw[256];
    __shared__ bool   is_last_b, is_last_g;
    if (sub == 1) sh4[lane] = sd;
    sw[tid] = w;
    __syncthreads();
    if (sub == 0) {
        const float4 o = sh4[lane];
        sd.x += o.x; sd.y += o.y; sd.z += o.z; sd.w += o.w;
        __stcs(reinterpret_cast<float4*>(g_S + ((size_t)(b * TILES + tile)) * DD + dg), sd);
    }

    // Block-reduce the word partial.
    #pragma unroll
    for (int s = 128; s > 0; s >>= 1) {
        if (tid < s) sw[tid] += sw[tid + s];
        __syncthreads();
    }
    if (tid == 0) {
        g_wordP[b * TILES + tile] = sw[0];
        __threadfence();
        // wraps to 0 after TILES arrivals -> self-resetting across replays
        unsigned prev = atomicInc(&g_ctrB[b], TILES - 1u);
        is_last_b = (prev == TILES - 1u);
    }
    __syncthreads();
    if (!is_last_b) return;

    // ---- Phase 2 (last block of this b): fold 64 partial slots, L2-hot ----
    __threadfence();  // acquire: see all 64 blocks' g_S writes for this b

    float4 s4 = make_float4(0.f, 0.f, 0.f, 0.f);
    const float* Sb = g_S + (size_t)b * TILES * DD;
    #pragma unroll
    for (int j = sub * (TILES / 2); j < (sub + 1) * (TILES / 2); j++) {
        const float4 v = *reinterpret_cast<const float4*>(Sb + (size_t)j * DD + dg);
        s4.x += v.x; s4.y += v.y; s4.z += v.z; s4.w += v.w;
    }
    __syncthreads();   // sh4 reuse
    if (sub == 1) sh4[lane] = s4;
    __syncthreads();
    float wsent = 0.f;
    if (sub == 0) {
        const float4 o = sh4[lane];
        s4.x += o.x; s4.y += o.y; s4.z += o.z; s4.w += o.w;
        const float invlen = 1.0f / (float)len;
        wsent = sl1(s4.x * invlen) + sl1(s4.y * invlen)
              + sl1(s4.z * invlen) + sl1(s4.w * invlen);
    }
    sw[tid] = wsent;
    __syncthreads();
    #pragma unroll
    for (int s = 128; s > 0; s >>= 1) {
        if (tid < s) sw[tid] += sw[tid + s];
        __syncthreads();
    }
    if (tid == 0) {
        g_sentB[b] = sw[0] * (1.0f / (float)DD);
        __threadfence();
        unsigned prev = atomicInc(&g_ctr, BB - 1u);
        is_last_g = (prev == BB - 1u);
    }
    __syncthreads();
    if (!is_last_g) return;

    // ---- Phase 3 (single final block): scalar combine, L2-hot ----
    __threadfence();

    float wsum = 0.f;
    #pragma unroll
    for (int i = tid; i < BB * TILES; i += 256) wsum += g_wordP[i];
    float ssum = 0.f;
    int   lsum = 0;
    if (tid < BB) { ssum = g_sentB[tid]; lsum = lens[tid]; }

    __shared__ float swd[256];
    __shared__ float ssn[256];
    __shared__ int   sln[256];
    swd[tid] = wsum; ssn[tid] = ssum; sln[tid] = lsum;
    __syncthreads();
    #pragma unroll
    for (int s = 128; s > 0; s >>= 1) {
        if (tid < s) {
            swd[tid] += swd[tid + s];
            ssn[tid] += ssn[tid + s];
            sln[tid] += sln[tid + s];
        }
        __syncthreads();
    }
    if (tid == 0) {
        const float n_valid = (float)sln[0] * (float)DD;  // <= 2^25, exact
        out[0] = swd[0] / n_valid + ssn[0] * (1.0f / (float)BB);
    }
}

extern "C" void kernel_launch(void* const* d_in, const int* in_sizes, int n_in,
                              void* d_out, int out_size) {
    const float* preds = (const float*)d_in[0];
    const float* targs = (const float*)d_in[1];
    const int*   lens  = (const int*)d_in[2];
    float* out = (float*)d_out;

    k_fused<<<dim3(TILES, BB), 256>>>(preds, targs, lens, out);
}

// round 16
// speedup vs baseline: 1.4058x; 1.0708x over previous
#include <cuda_runtime.h>

// Fixed shapes: preds/targets [32, 2048, 512] f32, lengths [32] i32.
#define BB 32
#define TT 2048
#define DD 512
#define TILES 64   // blocks (t-tiles) per batch row, strided t assignment
#define PFD 256    // prefetch distance in rows (2 iterations ahead)

// Scratch (device globals; every slot rewritten each launch; counters wrap
// back to 0 -> graph-replay-safe, no init kernel).
__device__ float    g_S[BB * TILES * DD];   // per-(b,tile,d) diff-sum partials, 4 MiB
__device__ float    g_wordP[BB * TILES];    // per-block word-loss partials (2048)
__device__ float    g_sentB[BB];            // per-b sentence term
__device__ unsigned g_ctrB[BB];             // per-b arrival counters (wrap at TILES-1)
__device__ unsigned g_ctr;                  // global arrival counter (wrap at BB-1)

__device__ __forceinline__ float sl1(float d) {
    float ad = fabsf(d);
    return ad < 1.0f ? 0.5f * d * d : ad - 0.5f;
}

// Fire-and-forget bulk L2 prefetch (no completion tracking).
__device__ __forceinline__ void pf_l2(const void* p, unsigned bytes) {
    asm volatile("cp.async.bulk.prefetch.L2.global [%0], %1;"
                 :: "l"(p), "r"(bytes) : "memory");
}

// One fused kernel. grid = (TILES, BB), block = 256 (2 t-rows x 128 float4 lanes).
// DRAM->L2 fill is driven by untracked bulk prefetches; demand loads are
// evict-first and hit L2. Single-row loop keeps regs <= 32 for 8 CTAs/SM.
__global__ __launch_bounds__(256, 8)
void k_fused(const float* __restrict__ preds,
             const float* __restrict__ targs,
             const int* __restrict__ lens,
             float* __restrict__ out) {
    const int b    = blockIdx.y;
    const int tile = blockIdx.x;
    const int tid  = threadIdx.x;
    const int sub  = tid >> 7;            // 0/1: which row of the pair
    const int lane = tid & 127;
    const int dg   = lane << 2;           // float4 column group (covers D=512)

    const int len = lens[b];

    // ---- Phase 1: stream valid rows once ----
    float4 sd = make_float4(0.f, 0.f, 0.f, 0.f);
    float  w  = 0.f;

    const float* pbase = preds + (size_t)b * TT * DD + dg;   // tid0: dg=0 -> row base
    const float* qbase = targs + (size_t)b * TT * DD + dg;
    const int step = 2 * TILES;           // 128 rows between this thread's rows

    // Prologue prefetch: first two iterations' rows (tid 0 only; dg==0 there).
    if (tid == 0) {
        #pragma unroll
        for (int j = 0; j < 4; j++) {
            const int r = tile + j * TILES;
            if (r < len) {
                pf_l2(pbase + (size_t)r * DD, 2048u);
                pf_l2(qbase + (size_t)r * DD, 2048u);
            }
        }
    }

    for (int t = tile + sub * TILES; t < len; t += step) {
        if (tid == 0) {
            // prefetch iteration k+2's two block-rows (both tensors)
            const int r0 = t + PFD;
            const int r1 = t + PFD + TILES;
            if (r0 < len) {
                pf_l2(pbase + (size_t)r0 * DD, 2048u);
                pf_l2(qbase + (size_t)r0 * DD, 2048u);
            }
            if (r1 < len) {
                pf_l2(pbase + (size_t)r1 * DD, 2048u);
                pf_l2(qbase + (size_t)r1 * DD, 2048u);
            }
        }
        const size_t o0 = (size_t)t * DD;
        const float4 pv = __ldcs(reinterpret_cast<const float4*>(pbase + o0));
        const float4 tv = __ldcs(reinterpret_cast<const float4*>(qbase + o0));
        float dx = pv.x - tv.x, dy = pv.y - tv.y;
        float dz = pv.z - tv.z, dw = pv.w - tv.w;
        sd.x += dx; sd.y += dy; sd.z += dz; sd.w += dw;
        w += sl1(dx) + sl1(dy) + sl1(dz) + sl1(dw);
    }

    // Combine sub0+sub1 diff-sums via shared; one slot per (b,tile).
    __shared__ float4 sh4[128];
    __shared__ float  sw[256];
    __shared__ bool   is_last_b, is_last_g;
    if (sub == 1) sh4[lane] = sd;
    sw[tid] = w;
    __syncthreads();
    if (sub == 0) {
        const float4 o = sh4[lane];
        sd.x += o.x; sd.y += o.y; sd.z += o.z; sd.w += o.w;
        __stcs(reinterpret_cast<float4*>(g_S + ((size_t)(b * TILES + tile)) * DD + dg), sd);
    }

    // Block-reduce the word partial.
    #pragma unroll
    for (int s = 128; s > 0; s >>= 1) {
        if (tid < s) sw[tid] += sw[tid + s];
        __syncthreads();
    }
    if (tid == 0) {
        g_wordP[b * TILES + tile] = sw[0];
        __threadfence();
        // wraps to 0 after TILES arrivals -> self-resetting across replays
        unsigned prev = atomicInc(&g_ctrB[b], TILES - 1u);
        is_last_b = (prev == TILES - 1u);
    }
    __syncthreads();
    if (!is_last_b) return;

    // ---- Phase 2 (last block of this b): fold 64 partial slots, L2-hot ----
    __threadfence();  // acquire: see all 64 blocks' g_S writes for this b

    float4 s4 = make_float4(0.f, 0.f, 0.f, 0.f);
    const float* Sb = g_S + (size_t)b * TILES * DD;
    #pragma unroll
    for (int j = sub * (TILES / 2); j < (sub + 1) * (TILES / 2); j++) {
        const float4 v = *reinterpret_cast<const float4*>(Sb + (size_t)j * DD + dg);
        s4.x += v.x; s4.y += v.y; s4.z += v.z; s4.w += v.w;
    }
    __syncthreads();   // sh4 reuse
    if (sub == 1) sh4[lane] = s4;
    __syncthreads();
    float wsent = 0.f;
    if (sub == 0) {
        const float4 o = sh4[lane];
        s4.x += o.x; s4.y += o.y; s4.z += o.z; s4.w += o.w;
        const float invlen = 1.0f / (float)len;
        wsent = sl1(s4.x * invlen) + sl1(s4.y * invlen)
              + sl1(s4.z * invlen) + sl1(s4.w * invlen);
    }
    sw[tid] = wsent;
    __syncthreads();
    #pragma unroll
    for (int s = 128; s > 0; s >>= 1) {
        if (tid < s) sw[tid] += sw[tid + s];
        __syncthreads();
    }
    if (tid == 0) {
        g_sentB[b] = sw[0] * (1.0f / (float)DD);
        __threadfence();
        unsigned prev = atomicInc(&g_ctr, BB - 1u);
        is_last_g = (prev == BB - 1u);
    }
    __syncthreads();
    if (!is_last_g) return;

    // ---- Phase 3 (single final block): scalar combine, L2-hot ----
    __threadfence();

    float wsum = 0.f;
    #pragma unroll
    for (int i = tid; i < BB * TILES; i += 256) wsum += g_wordP[i];
    float ssum = 0.f;
    int   lsum = 0;
    if (tid < BB) { ssum = g_sentB[tid]; lsum = lens[tid]; }

    __shared__ float swd[256];
    __shared__ float ssn[256];
    __shared__ int   sln[256];
    swd[tid] = wsum; ssn[tid] = ssum; sln[tid] = lsum;
    __syncthreads();
    #pragma unroll
    for (int s = 128; s > 0; s >>= 1) {
        if (tid < s) {
            swd[tid] += swd[tid + s];
            ssn[tid] += ssn[tid + s];
            sln[tid] += sln[tid + s];
        }
        __syncthreads();
    }
    if (tid == 0) {
        const float n_valid = (float)sln[0] * (float)DD;  // <= 2^25, exact
        out[0] = swd[0] / n_valid + ssn[0] * (1.0f / (float)BB);
    }
}

extern "C" void kernel_launch(void* const* d_in, const int* in_sizes, int n_in,
                              void* d_out, int out_size) {
    const float* preds = (const float*)d_in[0];
    const float* targs = (const float*)d_in[1];
    const int*   lens  = (const int*)d_in[2];
    float* out = (float*)d_out;

    k_fused<<<dim3(TILES, BB), 256>>>(preds, targs, lens, out);
}

// round 17
// speedup vs baseline: 1.4184x; 1.0089x over previous
#include <cuda_runtime.h>

// Fixed shapes: preds/targets [32, 2048, 512] f32, lengths [32] i32.
#define BB 32
#define TT 2048
#define DD 512
#define TILES 64   // blocks (t-tiles) per batch row, strided t assignment
#define PFD 384    // prefetch distance in rows (3 iterations ahead)

// Scratch (device globals; every slot rewritten each launch; counters wrap
// back to 0 -> graph-replay-safe, no init kernel).
__device__ float    g_S[BB * TILES * DD];   // per-(b,tile,d) diff-sum partials, 4 MiB
__device__ float    g_wordP[BB * TILES];    // per-block word-loss partials (2048)
__device__ float    g_sentB[BB];            // per-b sentence term
__device__ unsigned g_ctrB[BB];             // per-b arrival counters (wrap at TILES-1)
__device__ unsigned g_ctr;                  // global arrival counter (wrap at BB-1)

__device__ __forceinline__ float sl1(float d) {
    float ad = fabsf(d);
    return ad < 1.0f ? 0.5f * d * d : ad - 0.5f;
}

// Fire-and-forget bulk L2 prefetch (no completion tracking).
__device__ __forceinline__ void pf_l2(const void* p, unsigned bytes) {
    asm volatile("cp.async.bulk.prefetch.L2.global [%0], %1;"
                 :: "l"(p), "r"(bytes) : "memory");
}

// One fused kernel. grid = (TILES, BB), block = 256 (2 t-rows x 128 float4 lanes).
// DRAM->L2 fill driven by untracked bulk prefetches, issue split across two
// warps (tid0: preds, tid128: targs); demand loads evict-first, hit L2.
__global__ __launch_bounds__(256, 8)
void k_fused(const float* __restrict__ preds,
             const float* __restrict__ targs,
             const int* __restrict__ lens,
             float* __restrict__ out) {
    const int b    = blockIdx.y;
    const int tile = blockIdx.x;
    const int tid  = threadIdx.x;
    const int sub  = tid >> 7;            // 0/1: which row of the pair
    const int lane = tid & 127;
    const int dg   = lane << 2;           // float4 column group (covers D=512)

    const int len = lens[b];

    // ---- Phase 1: stream valid rows once ----
    float4 sd = make_float4(0.f, 0.f, 0.f, 0.f);
    float  w  = 0.f;

    const float* pbase = preds + (size_t)b * TT * DD + dg;   // lane0: dg=0 -> row base
    const float* qbase = targs + (size_t)b * TT * DD + dg;
    const int step = 2 * TILES;           // 128 rows between this thread's rows

    // Prologue prefetch: first three iterations' rows. tid0 covers preds,
    // tid128 covers targs (both have dg==0 -> pointer is the row base).
    if (lane == 0) {
        const float* base = (sub == 0) ? pbase : qbase;
        #pragma unroll
        for (int j = 0; j < 6; j++) {
            const int r = tile + j * TILES;
            if (r < len) pf_l2(base + (size_t)r * DD, 2048u);
        }
    }

    for (int t = tile + sub * TILES; t < len; t += step) {
        if (lane == 0) {
            // prefetch iteration k+3's two block-rows for this warp's tensor
            const float* base = (sub == 0) ? pbase : qbase;
            const int r0 = (t - sub * TILES) + PFD;        // normalize to tile base
            const int r1 = r0 + TILES;
            if (r0 < len) pf_l2(base + (size_t)r0 * DD, 2048u);
            if (r1 < len) pf_l2(base + (size_t)r1 * DD, 2048u);
        }
        const size_t o0 = (size_t)t * DD;
        const float4 pv = __ldcs(reinterpret_cast<const float4*>(pbase + o0));
        const float4 tv = __ldcs(reinterpret_cast<const float4*>(qbase + o0));
        float dx = pv.x - tv.x, dy = pv.y - tv.y;
        float dz = pv.z - tv.z, dw = pv.w - tv.w;
        sd.x += dx; sd.y += dy; sd.z += dz; sd.w += dw;
        w += sl1(dx) + sl1(dy) + sl1(dz) + sl1(dw);
    }

    // Combine sub0+sub1 diff-sums via shared; one slot per (b,tile).
    __shared__ float4 sh4[128];
    __shared__ float  sw[256];
    __shared__ bool   is_last_b, is_last_g;
    if (sub == 1) sh4[lane] = sd;
    sw[tid] = w;
    __syncthreads();
    if (sub == 0) {
        const float4 o = sh4[lane];
        sd.x += o.x; sd.y += o.y; sd.z += o.z; sd.w += o.w;
        __stcs(reinterpret_cast<float4*>(g_S + ((size_t)(b * TILES + tile)) * DD + dg), sd);
    }

    // Block-reduce the word partial.
    #pragma unroll
    for (int s = 128; s > 0; s >>= 1) {
        if (tid < s) sw[tid] += sw[tid + s];
        __syncthreads();
    }
    if (tid == 0) {
        g_wordP[b * TILES + tile] = sw[0];
        __threadfence();
        // wraps to 0 after TILES arrivals -> self-resetting across replays
        unsigned prev = atomicInc(&g_ctrB[b], TILES - 1u);
        is_last_b = (prev == TILES - 1u);
    }
    __syncthreads();
    if (!is_last_b) return;

    // ---- Phase 2 (last block of this b): fold 64 partial slots, L2-hot ----
    __threadfence();  // acquire: see all 64 blocks' g_S writes for this b

    float4 s4 = make_float4(0.f, 0.f, 0.f, 0.f);
    const float* Sb = g_S + (size_t)b * TILES * DD;
    #pragma unroll
    for (int j = sub * (TILES / 2); j < (sub + 1) * (TILES / 2); j++) {
        const float4 v = *reinterpret_cast<const float4*>(Sb + (size_t)j * DD + dg);
        s4.x += v.x; s4.y += v.y; s4.z += v.z; s4.w += v.w;
    }
    __syncthreads();   // sh4 reuse
    if (sub == 1) sh4[lane] = s4;
    __syncthreads();
    float wsent = 0.f;
    if (sub == 0) {
        const float4 o = sh4[lane];
        s4.x += o.x; s4.y += o.y; s4.z += o.z; s4.w += o.w;
        const float invlen = 1.0f / (float)len;
        wsent = sl1(s4.x * invlen) + sl1(s4.y * invlen)
              + sl1(s4.z * invlen) + sl1(s4.w * invlen);
    }
    sw[tid] = wsent;
    __syncthreads();
    #pragma unroll
    for (int s = 128; s > 0; s >>= 1) {
        if (tid < s) sw[tid] += sw[tid + s];
        __syncthreads();
    }
    if (tid == 0) {
        g_sentB[b] = sw[0] * (1.0f / (float)DD);
        __threadfence();
        unsigned prev = atomicInc(&g_ctr, BB - 1u);
        is_last_g = (prev == BB - 1u);
    }
    __syncthreads();
    if (!is_last_g) return;

    // ---- Phase 3 (single final block): scalar combine, L2-hot ----
    __threadfence();

    float wsum = 0.f;
    #pragma unroll
    for (int i = tid; i < BB * TILES; i += 256) wsum += g_wordP[i];
    float ssum = 0.f;
    int   lsum = 0;
    if (tid < BB) { ssum = g_sentB[tid]; lsum = lens[tid]; }

    __shared__ float swd[256];
    __shared__ float ssn[256];
    __shared__ int   sln[256];
    swd[tid] = wsum; ssn[tid] = ssum; sln[tid] = lsum;
    __syncthreads();
    #pragma unroll
    for (int s = 128; s > 0; s >>= 1) {
        if (tid < s) {
            swd[tid] += swd[tid + s];
            ssn[tid] += ssn[tid + s];
            sln[tid] += sln[tid + s];
        }
        __syncthreads();
    }
    if (tid == 0) {
        const float n_valid = (float)sln[0] * (float)DD;  // <= 2^25, exact
        out[0] = swd[0] / n_valid + ssn[0] * (1.0f / (float)BB);
    }
}

extern "C" void kernel_launch(void* const* d_in, const int* in_sizes, int n_in,
                              void* d_out, int out_size) {
    const float* preds = (const float*)d_in[0];
    const float* targs = (const float*)d_in[1];
    const int*   lens  = (const int*)d_in[2];
    float* out = (float*)d_out;

    k_fused<<<dim3(TILES, BB), 256>>>(preds, targs, lens, out);
}